// round 16
// baseline (speedup 1.0000x reference)
#include <cuda_runtime.h>
#include <math.h>

#define BATCH 16
#define NPOS0 102400
#define NPOS1 25600
#define NPOS2 6400
#define NPOS_TOT 134400
#define NBOX 25200
#define KPRE 2048
#define MAXDET 300
#define CONF_T_F 1e-4f
#define NMS_IOU_F 0.45f
#define KC_EIGEN 248

// ------------------------- device scratch (static, allowed) -----------------
__device__ float g_logits[(size_t)NPOS_TOT * 256];        // ~137.6 MB
__device__ float g_boxes[(size_t)BATCH * NBOX * 4];       // 6.45 MB
__device__ float g_scores[(size_t)BATCH * NBOX];          // 1.6 MB
__device__ int   g_labels[(size_t)BATCH * NBOX];          // 1.6 MB
__device__ unsigned long long g_topk[BATCH * KPRE];       // 256 KB

__constant__ float c_anch[3][3][2] = {
    {{10.f, 13.f}, {16.f, 30.f}, {33.f, 23.f}},
    {{30.f, 61.f}, {62.f, 45.f}, {59.f, 119.f}},
    {{116.f, 90.f}, {156.f, 198.f}, {373.f, 326.f}},
};

// ---- XLA CPU GenerateVF32Exp (exp-family; empirically equivalent to expf
// at all previously-decisive sites) ------------------------------------------
__device__ __forceinline__ float exp_vf32(float x) {
    float xc = fminf(fmaxf(x, -88.3762626647949f), 88.3762626647950f);
    float fx = floorf(fmaf(xc, 1.44269504088896341f, 0.5f));
    float tmp = __fmul_rn(0.693359375f, fx);
    float z   = __fmul_rn(-2.12194440e-4f, fx);
    float xr  = __fsub_rn(xc, tmp);
    xr = __fsub_rn(xr, z);
    z = __fmul_rn(xr, xr);
    float y = fmaf(xr, 1.9875691500E-4f, 1.3981999507E-3f);
    y = fmaf(y, xr, 8.3334519073E-3f);
    y = fmaf(y, xr, 4.1665795894E-2f);
    y = fmaf(y, xr, 1.6666665459E-1f);
    y = fmaf(y, xr, 5.0000001201E-1f);
    y = fmaf(y, z, xr);
    y = __fadd_rn(y, 1.0f);
    int n = (int)fx;
    float sc = __int_as_float((n + 127) << 23);
    return fmaxf(__fmul_rn(y, sc), x);
}
__device__ __forceinline__ float sg(float x) {
    return __fdiv_rn(1.0f, __fadd_rn(1.0f, exp_vf32(-x)));
}

// ------------------------- GEMM: logits = feat^T @ W ------------------------
// Eigen threaded blocking on aarch64 (default l1=16KB, mr=12, nr=4):
// kc = ((16384-192)/64) rounded down to mult of 8 = 248.
// K=512 -> panels 248/248/16; K=256 -> 248/8; K=128 -> monolithic.
// Each panel: sequential k-ascending FMA chain; panels combined by rn-adds
// in ascending order (gebp C += panel, C zero-initialized).
template <int K, int HW>
__global__ __launch_bounds__(256) void gemm_kernel(const float* __restrict__ feat,
                                                   const float* __restrict__ w,
                                                   int posBase) {
    __shared__ float As[8][64];
    __shared__ float Bs[8][256];
    const int t = threadIdx.x;
    const int tileStart = blockIdx.x * 64;
    const int tx = t & 31, ty = t >> 5;

    const int pp = t & 63;
    const int pos = tileStart + pp;
    const int bimg = pos / HW;
    const int s = pos - bimg * HW;
    const float* abase = feat + ((size_t)bimg * K) * HW + s;
    const int krow = t >> 6;  // 0..3

    float acc[8][8];
    float tmp[8][8];

#define GEMM_TILE8(KCBASE, ACCARR)                                             \
    {                                                                          \
        const int kcb = (KCBASE);                                              \
        _Pragma("unroll")                                                      \
        for (int r = 0; r < 2; r++) {                                          \
            int kk = r * 4 + krow;                                             \
            As[kk][pp] = abase[(size_t)(kcb + kk) * HW];                       \
        }                                                                      \
        _Pragma("unroll")                                                      \
        for (int r = 0; r < 8; r++) {                                          \
            int idx = r * 256 + t;                                             \
            int kk = idx >> 8, oo = idx & 255;                                 \
            Bs[kk][oo] = (oo < 255) ? w[(size_t)(kcb + kk) * 255 + oo] : 0.f;  \
        }                                                                      \
        __syncthreads();                                                       \
        _Pragma("unroll")                                                      \
        for (int k = 0; k < 8; k++) {                                          \
            float a[8], bv[8];                                                 \
            _Pragma("unroll")                                                  \
            for (int i = 0; i < 8; i++) a[i] = As[k][ty * 8 + i];              \
            _Pragma("unroll")                                                  \
            for (int j = 0; j < 8; j++) bv[j] = Bs[k][tx * 8 + j];             \
            _Pragma("unroll")                                                  \
            for (int i = 0; i < 8; i++)                                        \
                _Pragma("unroll")                                              \
                for (int j = 0; j < 8; j++)                                    \
                    ACCARR[i][j] = fmaf(a[i], bv[j], ACCARR[i][j]);            \
        }                                                                      \
        __syncthreads();                                                       \
    }

#pragma unroll 1
    for (int pbase = 0; pbase < K; pbase += KC_EIGEN) {
        const int pdepth = (K - pbase < KC_EIGEN) ? (K - pbase) : KC_EIGEN;
#pragma unroll
        for (int i = 0; i < 8; i++)
#pragma unroll
            for (int j = 0; j < 8; j++) tmp[i][j] = 0.f;

#pragma unroll 1
        for (int kc = 0; kc < pdepth; kc += 8) GEMM_TILE8(pbase + kc, tmp)

        if (pbase == 0) {
#pragma unroll
            for (int i = 0; i < 8; i++)
#pragma unroll
                for (int j = 0; j < 8; j++) acc[i][j] = tmp[i][j];
        } else {
#pragma unroll
            for (int i = 0; i < 8; i++)
#pragma unroll
                for (int j = 0; j < 8; j++)
                    acc[i][j] = __fadd_rn(acc[i][j], tmp[i][j]);
        }
    }
#undef GEMM_TILE8

    float* outp = g_logits + (size_t)(posBase + tileStart) * 256;
#pragma unroll
    for (int i = 0; i < 8; i++) {
#pragma unroll
        for (int j = 0; j < 8; j += 4) {
            float4 v = make_float4(acc[i][j], acc[i][j + 1], acc[i][j + 2], acc[i][j + 3]);
            *(float4*)&outp[(size_t)(ty * 8 + i) * 256 + tx * 8 + j] = v;
        }
    }
}

// ------------------------- decode: logits -> boxes/scores/labels ------------
__global__ __launch_bounds__(256) void decode_kernel(const float* __restrict__ bias0,
                                                     const float* __restrict__ bias1,
                                                     const float* __restrict__ bias2) {
    __shared__ float st[32][257];
    const int posBlk = blockIdx.x * 32;
    const int t = threadIdx.x;

    const float* src = g_logits + (size_t)posBlk * 256;
#pragma unroll
    for (int r = 0; r < 32; r++) {
        int idx = r * 256 + t;
        st[idx >> 8][idx & 255] = src[idx];
    }
    __syncthreads();

    if (t < 96) {
        const int pl = t & 31;
        const int a = t >> 5;
        const int pos = posBlk + pl;

        int HW, W, nOff, scale, rel;
        float stride;
        const float* bias;
        if (pos < NPOS0) {
            scale = 0; HW = 6400; W = 80; stride = 8.f; nOff = 0; bias = bias0; rel = pos;
        } else if (pos < NPOS0 + NPOS1) {
            scale = 1; HW = 1600; W = 40; stride = 16.f; nOff = 19200; bias = bias1; rel = pos - NPOS0;
        } else {
            scale = 2; HW = 400; W = 20; stride = 32.f; nOff = 24000; bias = bias2; rel = pos - NPOS0 - NPOS1;
        }
        const int bimg = rel / HW;
        const int sIdx = rel - bimg * HW;
        const float gy = (float)(sIdx / W);
        const float gx = (float)(sIdx % W);

        const float* L = &st[pl][a * 85];
        const float* bp = bias + a * 85;

        float px = __fadd_rn(L[0], bp[0]);
        float py = __fadd_rn(L[1], bp[1]);
        float pw = __fadd_rn(L[2], bp[2]);
        float ph = __fadd_rn(L[3], bp[3]);
        float po = __fadd_rn(L[4], bp[4]);

        float obj = sg(po);

        // Pass 1: max class logit (sigmoid monotone; ulp-collapse window below)
        float lmax = __fadd_rn(L[5], bp[5]);
#pragma unroll 4
        for (int j = 1; j < 80; j++) {
            float cl = __fadd_rn(L[5 + j], bp[5 + j]);
            if (cl > lmax) lmax = cl;
        }
        // Pass 2: first strict max over float products obj*sg(cls) within window
        const float win = __fsub_rn(lmax, 1e-5f);
        float best = -1.0f;
        int mi = 0;
        for (int j = 0; j < 80; j++) {
            float cl = __fadd_rn(L[5 + j], bp[5 + j]);
            if (cl >= win) {
                float v = __fmul_rn(obj, sg(cl));
                if (v > best) { best = v; mi = j; }
            }
        }

        float x = __fmul_rn(__fadd_rn(__fsub_rn(__fmul_rn(sg(px), 2.0f), 0.5f), gx), stride);
        float y = __fmul_rn(__fadd_rn(__fsub_rn(__fmul_rn(sg(py), 2.0f), 0.5f), gy), stride);
        float tw = __fmul_rn(sg(pw), 2.0f);
        float th = __fmul_rn(sg(ph), 2.0f);
        float wx = __fmul_rn(__fmul_rn(tw, tw), c_anch[scale][a][0]);
        float wy = __fmul_rn(__fmul_rn(th, th), c_anch[scale][a][1]);

        const int n = nOff + a * HW + sIdx;
        float* bx = &g_boxes[((size_t)bimg * NBOX + n) * 4];
        bx[0] = __fsub_rn(x, __fmul_rn(wx, 0.5f));
        bx[1] = __fsub_rn(y, __fmul_rn(wy, 0.5f));
        bx[2] = __fadd_rn(x, __fmul_rn(wx, 0.5f));
        bx[3] = __fadd_rn(y, __fmul_rn(wy, 0.5f));
        g_scores[(size_t)bimg * NBOX + n] = best;
        g_labels[(size_t)bimg * NBOX + n] = mi;
    }
}

// ------------------------- top-K select + sort per image --------------------
__device__ __forceinline__ unsigned long long make_key(float s, int i) {
    s = (s > CONF_T_F) ? s : 0.0f;
    return ((unsigned long long)__float_as_uint(s) << 32) |
           (unsigned long long)(0xFFFFFFFFu - (unsigned)i);
}

__global__ __launch_bounds__(1024) void topk_kernel() {
    const int b = blockIdx.x;
    const int t = threadIdx.x;
    const float* sc = g_scores + (size_t)b * NBOX;

    __shared__ unsigned int hist[256];
    __shared__ unsigned long long s_prefix;
    __shared__ int s_krem;
    if (t == 0) { s_prefix = 0ULL; s_krem = KPRE; }
    __syncthreads();

    for (int d = 7; d >= 0; d--) {
        if (t < 256) hist[t] = 0;
        __syncthreads();
        unsigned long long pref = s_prefix;
        for (int i = t; i < NBOX; i += 1024) {
            unsigned long long key = make_key(sc[i], i);
            bool ok = (d == 7) || ((key >> ((d + 1) * 8)) == (pref >> ((d + 1) * 8)));
            if (ok) atomicAdd(&hist[(unsigned)(key >> (d * 8)) & 255u], 1u);
        }
        __syncthreads();
        if (t == 0) {
            int krem = s_krem;
            unsigned cum = 0;
            int chosen = 0;
            for (int bin = 255; bin >= 0; bin--) {
                unsigned c = hist[bin];
                if (cum + c >= (unsigned)krem) { chosen = bin; s_krem = krem - (int)cum; break; }
                cum += c;
            }
            s_prefix = pref | ((unsigned long long)chosen << (d * 8));
        }
        __syncthreads();
    }
    const unsigned long long T = s_prefix;

    __shared__ unsigned long long keys[KPRE];
    __shared__ int cnt;
    if (t == 0) cnt = 0;
    for (int i = t; i < KPRE; i += 1024) keys[i] = 0ULL;
    __syncthreads();
    for (int i = t; i < NBOX; i += 1024) {
        unsigned long long key = make_key(sc[i], i);
        if (key >= T) {
            int p = atomicAdd(&cnt, 1);
            if (p < KPRE) keys[p] = key;
        }
    }
    __syncthreads();

    for (int kk = 2; kk <= KPRE; kk <<= 1) {
        for (int j = kk >> 1; j > 0; j >>= 1) {
            for (int i = t; i < KPRE; i += 1024) {
                int l = i ^ j;
                if (l > i) {
                    bool desc = ((i & kk) == 0);
                    unsigned long long a = keys[i], c = keys[l];
                    bool sw = desc ? (a < c) : (a > c);
                    if (sw) { keys[i] = c; keys[l] = a; }
                }
            }
            __syncthreads();
        }
    }
    for (int i = t; i < KPRE; i += 1024) g_topk[b * KPRE + i] = keys[i];
}

// ------------------------- NMS + output -------------------------------------
__global__ __launch_bounds__(256) void nms_kernel(float* __restrict__ out) {
    const int b = blockIdx.x;
    const int t = threadIdx.x;

    __shared__ float bx1[KPRE], by1[KPRE], bx2[KPRE], by2[KPRE], ar[KPRE];
    __shared__ unsigned char kp[KPRE];
    __shared__ unsigned char lb[KPRE];
    __shared__ int sel[MAXDET];
    __shared__ int cnt;

    for (int i = t; i < KPRE; i += 256) {
        unsigned long long key = g_topk[b * KPRE + i];
        float s = __uint_as_float((unsigned)(key >> 32));
        int idx = (int)(0xFFFFFFFFu - (unsigned)key);
        const float* gb = &g_boxes[((size_t)b * NBOX + idx) * 4];
        int l = g_labels[(size_t)b * NBOX + idx];
        float off = __fmul_rn((float)l, 4096.0f);
        float x1 = __fadd_rn(gb[0], off), y1 = __fadd_rn(gb[1], off);
        float x2 = __fadd_rn(gb[2], off), y2 = __fadd_rn(gb[3], off);
        bx1[i] = x1; by1[i] = y1; bx2[i] = x2; by2[i] = y2;
        ar[i] = __fmul_rn(fmaxf(__fsub_rn(x2, x1), 0.f), fmaxf(__fsub_rn(y2, y1), 0.f));
        lb[i] = (unsigned char)l;
        kp[i] = (s > CONF_T_F) ? 1 : 0;
    }
    __syncthreads();

    for (int i = 0; i < KPRE; i++) {
        if (!kp[i]) continue;
        float X1 = bx1[i], Y1 = by1[i], X2 = bx2[i], Y2 = by2[i], A = ar[i];
        for (int j = i + 1 + t; j < KPRE; j += 256) {
            if (!kp[j]) continue;
            float ix1 = fmaxf(X1, bx1[j]);
            float iy1 = fmaxf(Y1, by1[j]);
            float ix2 = fminf(X2, bx2[j]);
            float iy2 = fminf(Y2, by2[j]);
            float inter = __fmul_rn(fmaxf(__fsub_rn(ix2, ix1), 0.f),
                                    fmaxf(__fsub_rn(iy2, iy1), 0.f));
            float den = __fadd_rn(__fsub_rn(__fadd_rn(A, ar[j]), inter), 1e-9f);
            float iou = __fdiv_rn(inter, den);
            if (iou > NMS_IOU_F) kp[j] = 0;
        }
        __syncthreads();
    }

    if (t == 0) {
        int c = 0;
        for (int i = 0; i < KPRE && c < MAXDET; i++)
            if (kp[i]) sel[c++] = i;
        cnt = c;
    }
    __syncthreads();

    for (int r = t; r < MAXDET; r += 256) {
        float* ob = out + ((size_t)b * MAXDET + r) * 4;
        float* os = out + (size_t)BATCH * MAXDET * 4 + b * MAXDET + r;
        float* ol = out + (size_t)BATCH * MAXDET * 5 + b * MAXDET + r;
        if (r < cnt) {
            int i = sel[r];
            unsigned long long key = g_topk[b * KPRE + i];
            float s = __uint_as_float((unsigned)(key >> 32));
            int idx = (int)(0xFFFFFFFFu - (unsigned)key);
            const float* gb = &g_boxes[((size_t)b * NBOX + idx) * 4];
            ob[0] = gb[0]; ob[1] = gb[1]; ob[2] = gb[2]; ob[3] = gb[3];
            *os = s;
            *ol = (float)lb[i];
        } else {
            ob[0] = 0.f; ob[1] = 0.f; ob[2] = 0.f; ob[3] = 0.f;
            *os = 0.f;
            *ol = -1.f;
        }
    }
}

// ------------------------- launch -------------------------------------------
extern "C" void kernel_launch(void* const* d_in, const int* in_sizes, int n_in,
                              void* d_out, int out_size) {
    const float *f0 = 0, *f1 = 0, *f2 = 0, *w0 = 0, *w1 = 0, *w2 = 0;
    const float* bb[3] = {0, 0, 0};
    int nb = 0;
    for (int i = 0; i < n_in; i++) {
        const float* p = (const float*)d_in[i];
        switch (in_sizes[i]) {
            case 13107200: f0 = p; break;
            case 6553600:  f1 = p; break;
            case 3276800:  f2 = p; break;
            case 32640:    w0 = p; break;
            case 65280:    w1 = p; break;
            case 130560:   w2 = p; break;
            case 255:      if (nb < 3) bb[nb++] = p; break;
            default: break;
        }
    }
    if (!f0 || !f1 || !f2 || !w0 || !w1 || !w2 || nb < 3) return;

    gemm_kernel<128, 6400><<<NPOS0 / 64, 256>>>(f0, w0, 0);
    gemm_kernel<256, 1600><<<NPOS1 / 64, 256>>>(f1, w1, NPOS0);
    gemm_kernel<512, 400><<<NPOS2 / 64, 256>>>(f2, w2, NPOS0 + NPOS1);
    decode_kernel<<<NPOS_TOT / 32, 256>>>(bb[0], bb[1], bb[2]);
    topk_kernel<<<BATCH, 1024>>>();
    nms_kernel<<<BATCH, 256>>>((float*)d_out);
}

// round 17
// speedup vs baseline: 1.0155x; 1.0155x over previous
#include <cuda_runtime.h>
#include <math.h>

#define BATCH 16
#define NPOS0 102400
#define NPOS1 25600
#define NPOS2 6400
#define NPOS_TOT 134400
#define NBOX 25200
#define KPRE 2048
#define MAXDET 300
#define CONF_T_F 1e-4f
#define NMS_IOU_F 0.45f
#define KC_EIGEN 248

// ------------------------- device scratch (static, allowed) -----------------
__device__ float g_logits[(size_t)NPOS_TOT * 256];        // ~137.6 MB
__device__ float g_boxes[(size_t)BATCH * NBOX * 4];       // 6.45 MB
__device__ float g_scores[(size_t)BATCH * NBOX];          // 1.6 MB
__device__ int   g_labels[(size_t)BATCH * NBOX];          // 1.6 MB
__device__ unsigned long long g_topk[BATCH * KPRE];       // 256 KB

__constant__ float c_anch[3][3][2] = {
    {{10.f, 13.f}, {16.f, 30.f}, {33.f, 23.f}},
    {{30.f, 61.f}, {62.f, 45.f}, {59.f, 119.f}},
    {{116.f, 90.f}, {156.f, 198.f}, {373.f, 326.f}},
};

// ---- XLA CPU GenerateVF32Exp ------------------------------------------------
__device__ __forceinline__ float exp_vf32(float x) {
    float xc = fminf(fmaxf(x, -88.3762626647949f), 88.3762626647950f);
    float fx = floorf(fmaf(xc, 1.44269504088896341f, 0.5f));
    float tmp = __fmul_rn(0.693359375f, fx);
    float z   = __fmul_rn(-2.12194440e-4f, fx);
    float xr  = __fsub_rn(xc, tmp);
    xr = __fsub_rn(xr, z);
    z = __fmul_rn(xr, xr);
    float y = fmaf(xr, 1.9875691500E-4f, 1.3981999507E-3f);
    y = fmaf(y, xr, 8.3334519073E-3f);
    y = fmaf(y, xr, 4.1665795894E-2f);
    y = fmaf(y, xr, 1.6666665459E-1f);
    y = fmaf(y, xr, 5.0000001201E-1f);
    y = fmaf(y, z, xr);
    y = __fadd_rn(y, 1.0f);
    int n = (int)fx;
    float sc = __int_as_float((n + 127) << 23);
    return fmaxf(__fmul_rn(y, sc), x);
}
__device__ __forceinline__ float sg(float x) {
    return __fdiv_rn(1.0f, __fadd_rn(1.0f, exp_vf32(-x)));
}

// ------------------------- GEMM: logits = feat^T @ W ------------------------
// Eigen aarch64 blocking: kc=248. K=512 -> panels 248/248/16; K=256 -> 248/8;
// K=128 -> monolithic. Single 8x8 register accumulator per panel (no spill);
// panel sums combined via global read-modify-write with one rn-add each, in
// ascending panel order -> bit-identical ((P0+P1)+P2) chain as R16.
template <int K, int HW>
__global__ __launch_bounds__(256) void gemm_kernel(const float* __restrict__ feat,
                                                   const float* __restrict__ w,
                                                   int posBase) {
    __shared__ float As[8][64];
    __shared__ float Bs[8][256];
    const int t = threadIdx.x;
    const int tileStart = blockIdx.x * 64;
    const int tx = t & 31, ty = t >> 5;

    const int pp = t & 63;
    const int pos = tileStart + pp;
    const int bimg = pos / HW;
    const int s = pos - bimg * HW;
    const float* abase = feat + ((size_t)bimg * K) * HW + s;
    const int krow = t >> 6;  // 0..3

    float* outp = g_logits + (size_t)(posBase + tileStart) * 256;

    float acc[8][8];

#define GEMM_TILE8(KCBASE)                                                     \
    {                                                                          \
        const int kcb = (KCBASE);                                              \
        _Pragma("unroll")                                                      \
        for (int r = 0; r < 2; r++) {                                          \
            int kk = r * 4 + krow;                                             \
            As[kk][pp] = abase[(size_t)(kcb + kk) * HW];                       \
        }                                                                      \
        _Pragma("unroll")                                                      \
        for (int r = 0; r < 8; r++) {                                          \
            int idx = r * 256 + t;                                             \
            int kk = idx >> 8, oo = idx & 255;                                 \
            Bs[kk][oo] = (oo < 255) ? w[(size_t)(kcb + kk) * 255 + oo] : 0.f;  \
        }                                                                      \
        __syncthreads();                                                       \
        _Pragma("unroll")                                                      \
        for (int k = 0; k < 8; k++) {                                          \
            float a[8], bv[8];                                                 \
            _Pragma("unroll")                                                  \
            for (int i = 0; i < 8; i++) a[i] = As[k][ty * 8 + i];              \
            _Pragma("unroll")                                                  \
            for (int j = 0; j < 8; j++) bv[j] = Bs[k][tx * 8 + j];             \
            _Pragma("unroll")                                                  \
            for (int i = 0; i < 8; i++)                                        \
                _Pragma("unroll")                                              \
                for (int j = 0; j < 8; j++)                                    \
                    acc[i][j] = fmaf(a[i], bv[j], acc[i][j]);                  \
        }                                                                      \
        __syncthreads();                                                       \
    }

#pragma unroll 1
    for (int pbase = 0; pbase < K; pbase += KC_EIGEN) {
        const int pdepth = (K - pbase < KC_EIGEN) ? (K - pbase) : KC_EIGEN;
#pragma unroll
        for (int i = 0; i < 8; i++)
#pragma unroll
            for (int j = 0; j < 8; j++) acc[i][j] = 0.f;

#pragma unroll 1
        for (int kc = 0; kc < pdepth; kc += 8) GEMM_TILE8(pbase + kc)

        if (pbase == 0) {
#pragma unroll
            for (int i = 0; i < 8; i++) {
#pragma unroll
                for (int j = 0; j < 8; j += 4) {
                    float4 v = make_float4(acc[i][j], acc[i][j + 1],
                                           acc[i][j + 2], acc[i][j + 3]);
                    *(float4*)&outp[(size_t)(ty * 8 + i) * 256 + tx * 8 + j] = v;
                }
            }
        } else {
#pragma unroll
            for (int i = 0; i < 8; i++) {
#pragma unroll
                for (int j = 0; j < 8; j += 4) {
                    float4* p = (float4*)&outp[(size_t)(ty * 8 + i) * 256 + tx * 8 + j];
                    float4 v = *p;
                    v.x = __fadd_rn(v.x, acc[i][j]);
                    v.y = __fadd_rn(v.y, acc[i][j + 1]);
                    v.z = __fadd_rn(v.z, acc[i][j + 2]);
                    v.w = __fadd_rn(v.w, acc[i][j + 3]);
                    *p = v;
                }
            }
        }
    }
#undef GEMM_TILE8
}

// ------------------------- decode: logits -> boxes/scores/labels ------------
__global__ __launch_bounds__(256) void decode_kernel(const float* __restrict__ bias0,
                                                     const float* __restrict__ bias1,
                                                     const float* __restrict__ bias2) {
    __shared__ float st[32][257];
    const int posBlk = blockIdx.x * 32;
    const int t = threadIdx.x;

    const float* src = g_logits + (size_t)posBlk * 256;
#pragma unroll
    for (int r = 0; r < 32; r++) {
        int idx = r * 256 + t;
        st[idx >> 8][idx & 255] = src[idx];
    }
    __syncthreads();

    if (t < 96) {
        const int pl = t & 31;
        const int a = t >> 5;
        const int pos = posBlk + pl;

        int HW, W, nOff, scale, rel;
        float stride;
        const float* bias;
        if (pos < NPOS0) {
            scale = 0; HW = 6400; W = 80; stride = 8.f; nOff = 0; bias = bias0; rel = pos;
        } else if (pos < NPOS0 + NPOS1) {
            scale = 1; HW = 1600; W = 40; stride = 16.f; nOff = 19200; bias = bias1; rel = pos - NPOS0;
        } else {
            scale = 2; HW = 400; W = 20; stride = 32.f; nOff = 24000; bias = bias2; rel = pos - NPOS0 - NPOS1;
        }
        const int bimg = rel / HW;
        const int sIdx = rel - bimg * HW;
        const float gy = (float)(sIdx / W);
        const float gx = (float)(sIdx % W);

        const float* L = &st[pl][a * 85];
        const float* bp = bias + a * 85;

        float px = __fadd_rn(L[0], bp[0]);
        float py = __fadd_rn(L[1], bp[1]);
        float pw = __fadd_rn(L[2], bp[2]);
        float ph = __fadd_rn(L[3], bp[3]);
        float po = __fadd_rn(L[4], bp[4]);

        float obj = sg(po);

        float lmax = __fadd_rn(L[5], bp[5]);
#pragma unroll 4
        for (int j = 1; j < 80; j++) {
            float cl = __fadd_rn(L[5 + j], bp[5 + j]);
            if (cl > lmax) lmax = cl;
        }
        const float win = __fsub_rn(lmax, 1e-5f);
        float best = -1.0f;
        int mi = 0;
        for (int j = 0; j < 80; j++) {
            float cl = __fadd_rn(L[5 + j], bp[5 + j]);
            if (cl >= win) {
                float v = __fmul_rn(obj, sg(cl));
                if (v > best) { best = v; mi = j; }
            }
        }

        float x = __fmul_rn(__fadd_rn(__fsub_rn(__fmul_rn(sg(px), 2.0f), 0.5f), gx), stride);
        float y = __fmul_rn(__fadd_rn(__fsub_rn(__fmul_rn(sg(py), 2.0f), 0.5f), gy), stride);
        float tw = __fmul_rn(sg(pw), 2.0f);
        float th = __fmul_rn(sg(ph), 2.0f);
        float wx = __fmul_rn(__fmul_rn(tw, tw), c_anch[scale][a][0]);
        float wy = __fmul_rn(__fmul_rn(th, th), c_anch[scale][a][1]);

        const int n = nOff + a * HW + sIdx;
        float* bx = &g_boxes[((size_t)bimg * NBOX + n) * 4];
        bx[0] = __fsub_rn(x, __fmul_rn(wx, 0.5f));
        bx[1] = __fsub_rn(y, __fmul_rn(wy, 0.5f));
        bx[2] = __fadd_rn(x, __fmul_rn(wx, 0.5f));
        bx[3] = __fadd_rn(y, __fmul_rn(wy, 0.5f));
        g_scores[(size_t)bimg * NBOX + n] = best;
        g_labels[(size_t)bimg * NBOX + n] = mi;
    }
}

// ------------------------- top-K select + sort per image --------------------
__device__ __forceinline__ unsigned long long make_key(float s, int i) {
    s = (s > CONF_T_F) ? s : 0.0f;
    return ((unsigned long long)__float_as_uint(s) << 32) |
           (unsigned long long)(0xFFFFFFFFu - (unsigned)i);
}

__global__ __launch_bounds__(1024) void topk_kernel() {
    const int b = blockIdx.x;
    const int t = threadIdx.x;
    const float* sc = g_scores + (size_t)b * NBOX;

    __shared__ unsigned int hist[256];
    __shared__ unsigned long long s_prefix;
    __shared__ int s_krem;
    if (t == 0) { s_prefix = 0ULL; s_krem = KPRE; }
    __syncthreads();

    for (int d = 7; d >= 0; d--) {
        if (t < 256) hist[t] = 0;
        __syncthreads();
        unsigned long long pref = s_prefix;
        for (int i = t; i < NBOX; i += 1024) {
            unsigned long long key = make_key(sc[i], i);
            bool ok = (d == 7) || ((key >> ((d + 1) * 8)) == (pref >> ((d + 1) * 8)));
            if (ok) atomicAdd(&hist[(unsigned)(key >> (d * 8)) & 255u], 1u);
        }
        __syncthreads();
        if (t == 0) {
            int krem = s_krem;
            unsigned cum = 0;
            int chosen = 0;
            for (int bin = 255; bin >= 0; bin--) {
                unsigned c = hist[bin];
                if (cum + c >= (unsigned)krem) { chosen = bin; s_krem = krem - (int)cum; break; }
                cum += c;
            }
            s_prefix = pref | ((unsigned long long)chosen << (d * 8));
        }
        __syncthreads();
    }
    const unsigned long long T = s_prefix;

    __shared__ unsigned long long keys[KPRE];
    __shared__ int cnt;
    if (t == 0) cnt = 0;
    for (int i = t; i < KPRE; i += 1024) keys[i] = 0ULL;
    __syncthreads();
    for (int i = t; i < NBOX; i += 1024) {
        unsigned long long key = make_key(sc[i], i);
        if (key >= T) {
            int p = atomicAdd(&cnt, 1);
            if (p < KPRE) keys[p] = key;
        }
    }
    __syncthreads();

    for (int kk = 2; kk <= KPRE; kk <<= 1) {
        for (int j = kk >> 1; j > 0; j >>= 1) {
            for (int i = t; i < KPRE; i += 1024) {
                int l = i ^ j;
                if (l > i) {
                    bool desc = ((i & kk) == 0);
                    unsigned long long a = keys[i], c = keys[l];
                    bool sw = desc ? (a < c) : (a > c);
                    if (sw) { keys[i] = c; keys[l] = a; }
                }
            }
            __syncthreads();
        }
    }
    for (int i = t; i < KPRE; i += 1024) g_topk[b * KPRE + i] = keys[i];
}

// ------------------------- NMS + output -------------------------------------
__global__ __launch_bounds__(256) void nms_kernel(float* __restrict__ out) {
    const int b = blockIdx.x;
    const int t = threadIdx.x;

    __shared__ float bx1[KPRE], by1[KPRE], bx2[KPRE], by2[KPRE], ar[KPRE];
    __shared__ unsigned char kp[KPRE];
    __shared__ unsigned char lb[KPRE];
    __shared__ int sel[MAXDET];
    __shared__ int cnt;

    for (int i = t; i < KPRE; i += 256) {
        unsigned long long key = g_topk[b * KPRE + i];
        float s = __uint_as_float((unsigned)(key >> 32));
        int idx = (int)(0xFFFFFFFFu - (unsigned)key);
        const float* gb = &g_boxes[((size_t)b * NBOX + idx) * 4];
        int l = g_labels[(size_t)b * NBOX + idx];
        float off = __fmul_rn((float)l, 4096.0f);
        float x1 = __fadd_rn(gb[0], off), y1 = __fadd_rn(gb[1], off);
        float x2 = __fadd_rn(gb[2], off), y2 = __fadd_rn(gb[3], off);
        bx1[i] = x1; by1[i] = y1; bx2[i] = x2; by2[i] = y2;
        ar[i] = __fmul_rn(fmaxf(__fsub_rn(x2, x1), 0.f), fmaxf(__fsub_rn(y2, y1), 0.f));
        lb[i] = (unsigned char)l;
        kp[i] = (s > CONF_T_F) ? 1 : 0;
    }
    __syncthreads();

    for (int i = 0; i < KPRE; i++) {
        if (!kp[i]) continue;
        float X1 = bx1[i], Y1 = by1[i], X2 = bx2[i], Y2 = by2[i], A = ar[i];
        for (int j = i + 1 + t; j < KPRE; j += 256) {
            if (!kp[j]) continue;
            float ix1 = fmaxf(X1, bx1[j]);
            float iy1 = fmaxf(Y1, by1[j]);
            float ix2 = fminf(X2, bx2[j]);
            float iy2 = fminf(Y2, by2[j]);
            float inter = __fmul_rn(fmaxf(__fsub_rn(ix2, ix1), 0.f),
                                    fmaxf(__fsub_rn(iy2, iy1), 0.f));
            float den = __fadd_rn(__fsub_rn(__fadd_rn(A, ar[j]), inter), 1e-9f);
            float iou = __fdiv_rn(inter, den);
            if (iou > NMS_IOU_F) kp[j] = 0;
        }
        __syncthreads();
    }

    if (t == 0) {
        int c = 0;
        for (int i = 0; i < KPRE && c < MAXDET; i++)
            if (kp[i]) sel[c++] = i;
        cnt = c;
    }
    __syncthreads();

    for (int r = t; r < MAXDET; r += 256) {
        float* ob = out + ((size_t)b * MAXDET + r) * 4;
        float* os = out + (size_t)BATCH * MAXDET * 4 + b * MAXDET + r;
        float* ol = out + (size_t)BATCH * MAXDET * 5 + b * MAXDET + r;
        if (r < cnt) {
            int i = sel[r];
            unsigned long long key = g_topk[b * KPRE + i];
            float s = __uint_as_float((unsigned)(key >> 32));
            int idx = (int)(0xFFFFFFFFu - (unsigned)key);
            const float* gb = &g_boxes[((size_t)b * NBOX + idx) * 4];
            ob[0] = gb[0]; ob[1] = gb[1]; ob[2] = gb[2]; ob[3] = gb[3];
            *os = s;
            *ol = (float)lb[i];
        } else {
            ob[0] = 0.f; ob[1] = 0.f; ob[2] = 0.f; ob[3] = 0.f;
            *os = 0.f;
            *ol = -1.f;
        }
    }
}

// ------------------------- launch -------------------------------------------
extern "C" void kernel_launch(void* const* d_in, const int* in_sizes, int n_in,
                              void* d_out, int out_size) {
    const float *f0 = 0, *f1 = 0, *f2 = 0, *w0 = 0, *w1 = 0, *w2 = 0;
    const float* bb[3] = {0, 0, 0};
    int nb = 0;
    for (int i = 0; i < n_in; i++) {
        const float* p = (const float*)d_in[i];
        switch (in_sizes[i]) {
            case 13107200: f0 = p; break;
            case 6553600:  f1 = p; break;
            case 3276800:  f2 = p; break;
            case 32640:    w0 = p; break;
            case 65280:    w1 = p; break;
            case 130560:   w2 = p; break;
            case 255:      if (nb < 3) bb[nb++] = p; break;
            default: break;
        }
    }
    if (!f0 || !f1 || !f2 || !w0 || !w1 || !w2 || nb < 3) return;

    gemm_kernel<128, 6400><<<NPOS0 / 64, 256>>>(f0, w0, 0);
    gemm_kernel<256, 1600><<<NPOS1 / 64, 256>>>(f1, w1, NPOS0);
    gemm_kernel<512, 400><<<NPOS2 / 64, 256>>>(f2, w2, NPOS0 + NPOS1);
    decode_kernel<<<NPOS_TOT / 32, 256>>>(bb[0], bb[1], bb[2]);
    topk_kernel<<<BATCH, 1024>>>();
    nms_kernel<<<BATCH, 256>>>((float*)d_out);
}